// round 3
// baseline (speedup 1.0000x reference)
#include <cuda_runtime.h>
#include <math.h>

// Problem constants (match reference)
#define BATCH 4
#define CHANS 3
#define HDIM 512
#define WDIM 512
#define NPLANES 32
#define MAX_COC 50.0f
#define KMAX 31
#define HALO 15            // KMAX/2

// Tile config
#define TW 32
#define TH 16
#define SW (TW + 2*HALO)   // 62
#define SH (TH + 2*HALO)   // 46

__global__ __launch_bounds__(TW*TH) void dof_kernel(
    const float* __restrict__ img,
    const float* __restrict__ coc,
    float* __restrict__ out)
{
    __shared__ float tile[CHANS][SH*SW];

    const int tx = threadIdx.x, ty = threadIdx.y;
    const int tid = ty * TW + tx;
    const int bx0 = blockIdx.x * TW, by0 = blockIdx.y * TH;
    const int b = blockIdx.z;
    const int planeHW = HDIM * WDIM;

    // ---- Cooperative tile load (zero-pad outside image) ----
    for (int idx = tid; idx < SH*SW; idx += TW*TH) {
        const int sy = idx / SW;
        const int sx = idx - sy * SW;
        const int gy = by0 - HALO + sy;
        const int gx = bx0 - HALO + sx;
        const bool inb = (gy >= 0) & (gy < HDIM) & (gx >= 0) & (gx < WDIM);
        const int base = gy * WDIM + gx;
        #pragma unroll
        for (int c = 0; c < CHANS; c++) {
            tile[c][idx] = inb ? img[(b*CHANS + c)*planeHW + base] : 0.f;
        }
    }
    __syncthreads();

    const int x = bx0 + tx;
    const int y = by0 + ty;

    // ---- Per-pixel plane selection ----
    const float step = MAX_COC / (float)(NPLANES - 1);   // 50/31
    float c = coc[b*planeHW + y*WDIM + x];
    int p = (int)floorf(c / step + 0.5f);
    p = max(0, min(NPLANES - 1, p));

    // ---- Build this pixel's 1D Gaussian (zero-padded to KMAX, centered) ----
    float g[KMAX];
    if (p == 0) {
        #pragma unroll
        for (int j = 0; j < KMAX; j++) g[j] = 0.f;
        g[HALO] = 1.f;
    } else {
        const float cocp  = (float)p * step;
        const float sigma = cocp / 2.355f;
        int k = (int)(2.f * cocp + 1.f);
        if ((k & 1) == 0) k++;
        k = min(k, KMAX);
        const int half = k >> 1;
        const float inv2s2 = 1.f / (2.f * sigma * sigma);
        float s = 0.f;
        #pragma unroll
        for (int j = 0; j < KMAX; j++) {
            const int d = j - HALO;
            const int ad = (d < 0) ? -d : d;
            float v = (ad <= half) ? expf(-(float)(d*d) * inv2s2) : 0.f;
            g[j] = v;
            s += v;
        }
        const float inv = 1.f / s;
        #pragma unroll
        for (int j = 0; j < KMAX; j++) g[j] *= inv;
    }

    // ---- Per-pixel separable 31x31 gather (uniform control flow) ----
    for (int ch = 0; ch < CHANS; ch++) {
        const float* t = tile[ch];
        float acc = 0.f;
        #pragma unroll
        for (int dy = 0; dy < KMAX; dy++) {
            const float* row = t + (ty + dy) * SW + tx;
            float rs = 0.f;
            #pragma unroll
            for (int dx = 0; dx < KMAX; dx++) {
                rs += g[dx] * row[dx];
            }
            acc = fmaf(g[dy], rs, acc);
        }
        out[(b*CHANS + ch)*planeHW + y*WDIM + x] = acc;
    }
}

extern "C" void kernel_launch(void* const* d_in, const int* in_sizes, int n_in,
                              void* d_out, int out_size)
{
    const float* img = (const float*)d_in[0];   // [4,3,512,512]
    const float* coc = (const float*)d_in[1];   // [4,1,512,512]
    float* out = (float*)d_out;                 // [4,3,512,512]

    dim3 block(TW, TH);
    dim3 grid(WDIM / TW, HDIM / TH, BATCH);
    dof_kernel<<<grid, block>>>(img, coc, out);
}

// round 6
// speedup vs baseline: 2.7156x; 2.7156x over previous
#include <cuda_runtime.h>
#include <math.h>

// Problem constants (match reference)
#define BATCH 4
#define CHANS 3
#define HDIM 512
#define WDIM 512
#define NPLANES 32
#define MAX_COC 50.0f
#define KMAX 31
#define HALO 15            // KMAX/2

// Tile / thread config
#define R 4                 // outputs per thread, stacked in y
#define BTX 32
#define BTY 8
#define NTHREADS (BTX*BTY)          // 256
#define OUTROWS (BTY*R)             // 32 output rows per block
#define TILE_W (BTX + 2*HALO)       // 62
#define TILE_H (OUTROWS + 2*HALO)   // 62
#define NROWS (KMAX + R - 1)        // 34 rows touched per thread
#define NPAIR 16                    // 31 taps padded to 32 -> 16 f32x2 pairs

typedef unsigned long long u64;

__device__ __forceinline__ u64 pk(float lo, float hi) {
    u64 r;
    asm("mov.b64 %0, {%1, %2};" : "=l"(r) : "f"(lo), "f"(hi));
    return r;
}
__device__ __forceinline__ void upk(float& lo, float& hi, u64 v) {
    asm("mov.b64 {%0, %1}, %2;" : "=f"(lo), "=f"(hi) : "l"(v));
}
__device__ __forceinline__ u64 ffma2(u64 a, u64 b, u64 c) {
    u64 d;
    asm("fma.rn.f32x2 %0, %1, %2, %3;" : "=l"(d) : "l"(a), "l"(b), "l"(c));
    return d;
}
__device__ __forceinline__ u64 fmul2(u64 a, u64 b) {
    u64 d;
    asm("mul.rn.f32x2 %0, %1, %2;" : "=l"(d) : "l"(a), "l"(b));
    return d;
}

__global__ __launch_bounds__(NTHREADS) void dof_kernel(
    const float* __restrict__ img,
    const float* __restrict__ coc,
    float* __restrict__ out)
{
    __shared__ float tile[CHANS][TILE_H * TILE_W];
    __shared__ float gtab[NPLANES * KMAX];   // normalized, zero-padded, centered

    const int tx = threadIdx.x, ty = threadIdx.y;
    const int tid = ty * BTX + tx;
    const int bx0 = blockIdx.x * BTX;
    const int by0 = blockIdx.y * OUTROWS;
    const int b   = blockIdx.z;
    const int planeHW = HDIM * WDIM;
    const float step = MAX_COC / (float)(NPLANES - 1);   // 50/31

    // ---- Build normalized per-plane 1D Gaussian table (one plane per thread) ----
    if (tid < NPLANES) {
        const int p = tid;
        float g[KMAX];
        if (p == 0) {
            #pragma unroll
            for (int j = 0; j < KMAX; j++) g[j] = 0.f;
            g[HALO] = 1.f;
        } else {
            const float cocp  = (float)p * step;
            const float sigma = cocp / 2.355f;
            int k = (int)(2.f * cocp + 1.f);
            if ((k & 1) == 0) k++;
            k = min(k, KMAX);
            const int half = k >> 1;
            const float inv2s2 = 1.f / (2.f * sigma * sigma);
            float s = 0.f;
            #pragma unroll
            for (int j = 0; j < KMAX; j++) {
                const int d = j - HALO;
                const int ad = (d < 0) ? -d : d;
                float v = (ad <= half) ? expf(-(float)(d*d) * inv2s2) : 0.f;
                g[j] = v;
                s += v;
            }
            const float inv = 1.f / s;
            #pragma unroll
            for (int j = 0; j < KMAX; j++) g[j] *= inv;
        }
        #pragma unroll
        for (int j = 0; j < KMAX; j++) gtab[p * KMAX + j] = g[j];
    }

    // ---- Cooperative tile load (zero-pad outside image) ----
    for (int idx = tid; idx < TILE_H * TILE_W; idx += NTHREADS) {
        const int sy = idx / TILE_W;
        const int sx = idx - sy * TILE_W;
        const int gy = by0 - HALO + sy;
        const int gx = bx0 - HALO + sx;
        const bool inb = (gy >= 0) & (gy < HDIM) & (gx >= 0) & (gx < WDIM);
        const int base = gy * WDIM + gx;
        #pragma unroll
        for (int c = 0; c < CHANS; c++) {
            tile[c][idx] = inb ? img[(b*CHANS + c)*planeHW + base] : 0.f;
        }
    }
    __syncthreads();

    const int x   = bx0 + tx;
    const int tyR = ty * R;

    // ---- Per-output plane selection + packed horizontal weights (registers) ----
    int pj[R];
    u64 gp[R][NPAIR];
    #pragma unroll
    for (int j = 0; j < R; j++) {
        const int y = by0 + tyR + j;
        float c = coc[b*planeHW + y*WDIM + x];
        int p = (int)floorf(c / step + 0.5f);
        p = max(0, min(NPLANES - 1, p));
        pj[j] = p;
        const float* gr = &gtab[p * KMAX];
        #pragma unroll
        for (int m = 0; m < NPAIR; m++) {
            const float lo = gr[2*m];
            const float hi = (2*m + 1 < KMAX) ? gr[2*m + 1] : 0.f;
            gp[j][m] = pk(lo, hi);
        }
    }

    // ---- Main gather: each tile row loaded once, consumed by R outputs ----
    #pragma unroll 1
    for (int ch = 0; ch < CHANS; ch++) {
        const float* t = tile[ch];
        u64 acc[R];
        #pragma unroll
        for (int j = 0; j < R; j++) acc[j] = pk(0.f, 0.f);

        #pragma unroll 1
        for (int rr = 0; rr < NROWS; rr++) {
            const float* rowp = t + (tyR + rr) * TILE_W + tx;
            // pack 32 taps (tap 31 exists in the tile; its weight is 0)
            u64 tp[NPAIR];
            #pragma unroll
            for (int m = 0; m < NPAIR; m++) {
                tp[m] = pk(rowp[2*m], rowp[2*m + 1]);
            }
            #pragma unroll
            for (int j = 0; j < R; j++) {
                const int vy = rr - j;
                const bool valid = (vy >= 0) & (vy <= KMAX - 1);
                const int cvy = min(max(vy, 0), KMAX - 1);
                float gv = 0.f;
                if (valid) gv = gtab[pj[j] * KMAX + cvy];
                // packed horizontal inner product (16 FFMA2)
                u64 rsp = fmul2(gp[j][0], tp[0]);
                #pragma unroll
                for (int m = 1; m < NPAIR; m++) {
                    rsp = ffma2(gp[j][m], tp[m], rsp);
                }
                acc[j] = ffma2(pk(gv, gv), rsp, acc[j]);
            }
        }

        #pragma unroll
        for (int j = 0; j < R; j++) {
            float lo, hi;
            upk(lo, hi, acc[j]);
            const int y = by0 + tyR + j;
            out[(b*CHANS + ch)*planeHW + y*WDIM + x] = lo + hi;
        }
    }
}

extern "C" void kernel_launch(void* const* d_in, const int* in_sizes, int n_in,
                              void* d_out, int out_size)
{
    const float* img = (const float*)d_in[0];   // [4,3,512,512]
    const float* coc = (const float*)d_in[1];   // [4,1,512,512]
    float* out = (float*)d_out;                 // [4,3,512,512]

    dim3 block(BTX, BTY);
    dim3 grid(WDIM / BTX, HDIM / OUTROWS, BATCH);
    dof_kernel<<<grid, block>>>(img, coc, out);
}

// round 7
// speedup vs baseline: 3.0263x; 1.1144x over previous
#include <cuda_runtime.h>
#include <math.h>

// Problem constants (match reference)
#define BATCH 4
#define CHANS 3
#define HDIM 512
#define WDIM 512
#define NPLANES 32
#define MAX_COC 50.0f
#define KMAX 31
#define HALO 15            // KMAX/2
#define NSYM 16            // symmetric half-kernel length (m = 0..15)

// Tile / thread config
#define R 4                 // outputs per thread, stacked in y
#define BTX 32
#define BTY 8
#define NTHREADS (BTX*BTY)          // 256
#define OUTROWS (BTY*R)             // 32 output rows per block
#define TILE_W (BTX + 2*HALO)       // 62
#define TILE_H (OUTROWS + 2*HALO)   // 62
#define NROWS (KMAX + R - 1)        // 34 rows touched per thread
#define NPQ 8                       // 16 sym taps -> 8 f32x2 pairs

typedef unsigned long long u64;

__device__ __forceinline__ u64 pk(float lo, float hi) {
    u64 r;
    asm("mov.b64 %0, {%1, %2};" : "=l"(r) : "f"(lo), "f"(hi));
    return r;
}
__device__ __forceinline__ void upk(float& lo, float& hi, u64 v) {
    asm("mov.b64 {%0, %1}, %2;" : "=f"(lo), "=f"(hi) : "l"(v));
}
__device__ __forceinline__ u64 ffma2(u64 a, u64 b, u64 c) {
    u64 d;
    asm("fma.rn.f32x2 %0, %1, %2, %3;" : "=l"(d) : "l"(a), "l"(b), "l"(c));
    return d;
}
__device__ __forceinline__ u64 fmul2(u64 a, u64 b) {
    u64 d;
    asm("mul.rn.f32x2 %0, %1, %2;" : "=l"(d) : "l"(a), "l"(b));
    return d;
}

__global__ __launch_bounds__(NTHREADS, 2) void dof_kernel(
    const float* __restrict__ img,
    const float* __restrict__ coc,
    float* __restrict__ out)
{
    __shared__ float tile[CHANS][TILE_H * TILE_W];       // 46128 B
    // gs[m][p] = g_p[15+m] = g_p[15-m]  (symmetric half, transposed:
    // lanes index by plane p -> distinct banks or same-address broadcast)
    __shared__ float gs[NSYM * NPLANES];                 // 2048 B

    const int tx = threadIdx.x, ty = threadIdx.y;
    const int tid = ty * BTX + tx;
    const int bx0 = blockIdx.x * BTX;
    const int by0 = blockIdx.y * OUTROWS;
    const int b   = blockIdx.z;
    const int planeHW = HDIM * WDIM;
    const float step = MAX_COC / (float)(NPLANES - 1);   // 50/31

    // ---- Build normalized per-plane symmetric Gaussian half-table ----
    if (tid < NPLANES) {
        const int p = tid;
        float g[KMAX];
        if (p == 0) {
            #pragma unroll
            for (int j = 0; j < KMAX; j++) g[j] = 0.f;
            g[HALO] = 1.f;
        } else {
            const float cocp  = (float)p * step;
            const float sigma = cocp / 2.355f;
            int k = (int)(2.f * cocp + 1.f);
            if ((k & 1) == 0) k++;
            k = min(k, KMAX);
            const int half = k >> 1;
            const float inv2s2 = 1.f / (2.f * sigma * sigma);
            float s = 0.f;
            #pragma unroll
            for (int j = 0; j < KMAX; j++) {
                const int d = j - HALO;
                const int ad = (d < 0) ? -d : d;
                float v = (ad <= half) ? expf(-(float)(d*d) * inv2s2) : 0.f;
                g[j] = v;
                s += v;
            }
            const float inv = 1.f / s;
            #pragma unroll
            for (int j = 0; j < KMAX; j++) g[j] *= inv;
        }
        #pragma unroll
        for (int m = 0; m < NSYM; m++) gs[m * NPLANES + p] = g[HALO + m];
    }

    // ---- Cooperative tile load (zero-pad outside image) ----
    for (int idx = tid; idx < TILE_H * TILE_W; idx += NTHREADS) {
        const int sy = idx / TILE_W;
        const int sx = idx - sy * TILE_W;
        const int gy = by0 - HALO + sy;
        const int gx = bx0 - HALO + sx;
        const bool inb = (gy >= 0) & (gy < HDIM) & (gx >= 0) & (gx < WDIM);
        const int base = gy * WDIM + gx;
        #pragma unroll
        for (int c = 0; c < CHANS; c++) {
            tile[c][idx] = inb ? img[(b*CHANS + c)*planeHW + base] : 0.f;
        }
    }
    __syncthreads();

    const int x   = bx0 + tx;
    const int tyR = ty * R;

    // ---- Per-output plane selection + packed symmetric horizontal weights ----
    int pj[R];
    u64 hp[R][NPQ];          // 64 registers total
    #pragma unroll
    for (int j = 0; j < R; j++) {
        const int y = by0 + tyR + j;
        float c = coc[b*planeHW + y*WDIM + x];
        int p = (int)floorf(c / step + 0.5f);
        p = max(0, min(NPLANES - 1, p));
        pj[j] = p;
        #pragma unroll
        for (int q = 0; q < NPQ; q++) {
            hp[j][q] = pk(gs[(2*q) * NPLANES + p], gs[(2*q + 1) * NPLANES + p]);
        }
    }

    // ---- Main gather: each tile row loaded once, consumed by R outputs ----
    #pragma unroll 1
    for (int ch = 0; ch < CHANS; ch++) {
        const float* t = tile[ch];
        u64 acc[R];
        #pragma unroll
        for (int j = 0; j < R; j++) acc[j] = pk(0.f, 0.f);

        #pragma unroll 1
        for (int rr = 0; rr < NROWS; rr++) {
            const float* rowp = t + (tyR + rr) * TILE_W + tx;
            // symmetric pre-adds: s_m = row[15-m] + row[15+m], s_0 = row[15]
            // (31 LDS + 15 FADD, shared across all R outputs)
            u64 sp[NPQ];
            {
                const float s0 = rowp[HALO];
                const float s1 = rowp[HALO-1] + rowp[HALO+1];
                sp[0] = pk(s0, s1);
                #pragma unroll
                for (int q = 1; q < NPQ; q++) {
                    const int m0 = 2*q, m1 = 2*q + 1;
                    const float a0 = rowp[HALO-m0] + rowp[HALO+m0];
                    const float a1 = rowp[HALO-m1] + rowp[HALO+m1];
                    sp[q] = pk(a0, a1);
                }
            }
            #pragma unroll
            for (int j = 0; j < R; j++) {
                const int vy = rr - j;                       // [-3, 33]
                const bool valid = (vy >= 0) & (vy <= KMAX - 1);
                int m = vy - HALO; m = (m < 0) ? -m : m;     // |vy-15|
                m = min(m, NSYM - 1);
                float gv = 0.f;
                if (valid) gv = gs[m * NPLANES + pj[j]];
                // packed symmetric horizontal inner product (8 FFMA2)
                u64 rsp = fmul2(hp[j][0], sp[0]);
                #pragma unroll
                for (int q = 1; q < NPQ; q++) {
                    rsp = ffma2(hp[j][q], sp[q], rsp);
                }
                acc[j] = ffma2(pk(gv, gv), rsp, acc[j]);
            }
        }

        #pragma unroll
        for (int j = 0; j < R; j++) {
            float lo, hi;
            upk(lo, hi, acc[j]);
            const int y = by0 + tyR + j;
            out[(b*CHANS + ch)*planeHW + y*WDIM + x] = lo + hi;
        }
    }
}

extern "C" void kernel_launch(void* const* d_in, const int* in_sizes, int n_in,
                              void* d_out, int out_size)
{
    const float* img = (const float*)d_in[0];   // [4,3,512,512]
    const float* coc = (const float*)d_in[1];   // [4,1,512,512]
    float* out = (float*)d_out;                 // [4,3,512,512]

    dim3 block(BTX, BTY);
    dim3 grid(WDIM / BTX, HDIM / OUTROWS, BATCH);
    dof_kernel<<<grid, block>>>(img, coc, out);
}